// round 15
// baseline (speedup 1.0000x reference)
#include <cuda_runtime.h>
#include <cuda_fp16.h>
#include <math.h>
#include <stdint.h>

// Problem constants
#define Bsz   4
#define Lsz   4096
#define Wsz   2560
#define Hsz   10
#define BLKsz 256
#define Msz   (Bsz * Lsz)            // 16384 tokens

constexpr size_t TOT = (size_t)Bsz * Lsz * Wsz;   // 41,943,040 elements
constexpr int NMB = Msz / 128;                    // 128 m-blocks (= scan chunks)
constexpr int CPS = Lsz / 128;                    // 32 chunks per sequence

// Scratch (allocation-free: static device globals)
// Prepacked fp16 B fragments, paired n-tiles:
// [h][kt(16)][gate(2)][pair(16)][lane(32) x uint4]
__device__ uint32_t g_wfrag[10 * 16 * 2 * 16 * 128];
// fp16 row-major copy of x (for cp.async A staging)
__device__ __align__(16) __half g_xh[TOT];
// Decoupled-lookback state, indexed [mblock(128)][wch(2560)]
__device__ float2  g_pA  [NMB * Wsz];      // per-chunk partial (A, h)
__device__ float   g_pH  [NMB * Wsz];      // per-chunk inclusive prefix h
__device__ int     g_flag[NMB * Wsz];      // 0=none, 1=partial, 2=prefix

// ===========================================================================
// Helpers
// ===========================================================================
__device__ __forceinline__ uint32_t smem_u32(const void* p) {
    uint32_t a;
    asm("{ .reg .u64 t; cvta.to.shared.u64 t, %1; cvt.u32.u64 %0, t; }"
        : "=r"(a) : "l"(p));
    return a;
}

__device__ __forceinline__ uint32_t pack_h2(float lo, float hi) {
    __half2 t;
    t.x = __float2half_rn(lo);
    t.y = __float2half_rn(hi);
    return *reinterpret_cast<uint32_t*>(&t);
}

__device__ __forceinline__ void ldm_x4(uint32_t (&r)[4], uint32_t addr) {
    asm volatile("ldmatrix.sync.aligned.m8n8.x4.shared.b16 {%0,%1,%2,%3}, [%4];"
                 : "=r"(r[0]), "=r"(r[1]), "=r"(r[2]), "=r"(r[3]) : "r"(addr));
}

__device__ __forceinline__ void mma16816(float (&c)[4], const uint32_t (&a)[4],
                                         uint32_t b0, uint32_t b1) {
    asm volatile(
        "mma.sync.aligned.m16n8k16.row.col.f32.f16.f16.f32 "
        "{%0,%1,%2,%3}, {%4,%5,%6,%7}, {%8,%9}, {%0,%1,%2,%3};"
        : "+f"(c[0]), "+f"(c[1]), "+f"(c[2]), "+f"(c[3])
        : "r"(a[0]), "r"(a[1]), "r"(a[2]), "r"(a[3]), "r"(b0), "r"(b1));
}

__device__ __forceinline__ void cp_async16(uint32_t smem_dst, const void* gsrc) {
    asm volatile("cp.async.ca.shared.global [%0], [%1], 16;"
                 :: "r"(smem_dst), "l"(gsrc) : "memory");
}
__device__ __forceinline__ void cp_commit() {
    asm volatile("cp.async.commit_group;" ::: "memory");
}
__device__ __forceinline__ void cp_wait_all() {
    asm volatile("cp.async.wait_group 0;" ::: "memory");
}

__device__ __forceinline__ int ld_acq(const int* p) {
    int v;
    asm volatile("ld.acquire.gpu.global.b32 %0, [%1];" : "=r"(v) : "l"(p) : "memory");
    return v;
}
__device__ __forceinline__ void st_rel(int* p, int v) {
    asm volatile("st.release.gpu.global.b32 [%0], %1;" :: "l"(p), "r"(v) : "memory");
}

// ===========================================================================
// Merged prepack: x -> fp16 row-major copy (all threads) and, for the first
// 327,680 threads, W -> fp16 HMMA b-fragments + lookback flag clear.
// Grid = TOT/8 threads (20480 blocks x 256).
// ===========================================================================
__global__ __launch_bounds__(256)
void prepack_kernel(const float* __restrict__ x,
                    const float* __restrict__ wgx,
                    const float* __restrict__ wga)
{
    size_t t = (size_t)blockIdx.x * blockDim.x + threadIdx.x;   // < TOT/8

    // x -> fp16 (8 elements per thread)
    {
        const float4* src = reinterpret_cast<const float4*>(x) + t * 2;
        float4 v0 = src[0];
        float4 v1 = src[1];
        uint4 u;
        u.x = pack_h2(v0.x, v0.y);
        u.y = pack_h2(v0.z, v0.w);
        u.z = pack_h2(v1.x, v1.y);
        u.w = pack_h2(v1.z, v1.w);
        reinterpret_cast<uint4*>(g_xh)[t] = u;
    }

    if (t < (size_t)NMB * Wsz) {
        int ti = (int)t;
        g_flag[ti] = 0;

        int lane = ti & 31;
        int blk  = ti >> 5;           // 0..10239
        int nt = blk & 31;
        int rest = blk >> 5;
        int g  = rest & 1;
        int rest2 = rest >> 1;
        int kt = rest2 & 15;
        int h  = rest2 >> 4;

        const float* wsrc = (g ? wga : wgx) + (size_t)h * BLKsz * BLKsz;
        int k0 = kt * 16 + (lane & 3) * 2;
        int n  = nt * 8 + (lane >> 2);
        const float* p = wsrc + (size_t)k0 * BLKsz + n;

        uint32_t b0 = pack_h2(p[0],          p[BLKsz]);
        uint32_t b1 = pack_h2(p[8 * BLKsz],  p[9 * BLKsz]);

        uint32_t base = ((uint32_t)(((h * 16 + kt) * 2 + g) * 16 + (nt >> 1)) << 7)
                        + lane * 4 + (nt & 1) * 2;
        g_wfrag[base + 0] = b0;
        g_wfrag[base + 1] = b1;
    }
}

// ===========================================================================
// Fused kernel: fp16 mma.sync gate GEMM + pointwise + in-SMEM scan.
// CTA: 128 tokens x 64 channels x one head. Warp grid 4(m) x 2(n).
// A staged CTA-wide via cp.async, K-chunk = 64 (4 ksteps / stage, 4 barriers);
// B staged once. Epilogue x loads hoisted above the final k-loop barrier.
// Scan buffer aliases the GEMM region.
// ===========================================================================
#define AROW 144     // bytes per A smem row (128B data + 16B pad)
#define ASTAGE 18432 // 128 rows * 144B per stage
#define SCROW 66     // float2 slots per s_scan row (64 data + 2 pad)

// dynamic smem layout (bytes) — GEMM phase
#define OFF_A    0                       // 36,864 (2 stages x 128 x 144)
#define OFF_BF   36864                   // 65,536 (B fragments, whole K)
// scan phase (aliases GEMM region after final barrier): sscan at 0 (67,584)
#define OFF_SC   0
#define OFF_SEG  102400                  // 2,048
#define OFF_CAR  104448                  // 256
#define OFF_BX   104704                  // 256
#define OFF_BA   104960                  // 256
#define OFF_SP   105216                  // 256
#define FUSED_SMEM 105472

__global__ __launch_bounds__(256, 2)
void fused_kernel(const float* __restrict__ x,
                  const float* __restrict__ bgx,
                  const float* __restrict__ bga,
                  const float* __restrict__ apar,
                  const float* __restrict__ h0,
                  float* __restrict__ out)
{
    extern __shared__ char dynsm[];
    uint4*    smBf  = reinterpret_cast<uint4*>(dynsm + OFF_BF);     // [2][16][4][32]
    float2*   sscan = reinterpret_cast<float2*>(dynsm + OFF_SC);    // [128][66]
    float2*   sseg  = reinterpret_cast<float2*>(dynsm + OFF_SEG);   // [4][64]
    float*    scar  = reinterpret_cast<float*>(dynsm + OFF_CAR);    // [64]
    float*    s_bx  = reinterpret_cast<float*>(dynsm + OFF_BX);
    float*    s_ba  = reinterpret_cast<float*>(dynsm + OFF_BA);
    float*    s_sp  = reinterpret_cast<float*>(dynsm + OFF_SP);

    const int tid = threadIdx.x;
    const int w   = tid >> 5;
    const int l   = tid & 31;
    const int mw  = w & 3;                   // warp m-group (32 rows)
    const int ng  = w >> 2;                  // warp n-group (32 cols)
    const int hd   = blockIdx.x >> 2;        // 0..9
    const int yblk = blockIdx.x & 3;         // 0..3
    const int n0   = yblk * 64;
    const int mb   = blockIdx.y;             // m-block == scan chunk
    const int m0   = mb * 128;
    const int bseq = m0 / Lsz;               // batch index
    const int cseq = (m0 % Lsz) / 128;       // chunk within sequence

    if (tid < 64) {
        int ch = hd * BLKsz + n0 + tid;
        s_bx[tid] = bgx[ch];
        s_ba[tid] = bga[ch];
        s_sp[tid] = log1pf(expf(apar[ch]));
    }

    // A cp.async roles: row = tid/2, half = tid&1 (64B of the 128B chunk row)
    const int arow  = tid >> 1;
    const int ahalf = tid & 1;
    const __half* xh_base = g_xh + (size_t)(m0 + arow) * Wsz
                            + hd * BLKsz + ahalf * 32;
    const uint32_t smA_u = smem_u32(dynsm + OFF_A);
    const uint32_t a_dst_base = smA_u + arow * AROW + ahalf * 64;

    auto issueA = [&](int chunk) {
        uint32_t dst = a_dst_base + (chunk & 1) * ASTAGE;
        const __half* src = xh_base + chunk * 64;
        cp_async16(dst,      src);
        cp_async16(dst + 16, src + 8);
        cp_async16(dst + 32, src + 16);
        cp_async16(dst + 48, src + 24);
        cp_commit();
    };

    // prologue: A chunk 0 + one-shot B stage
    issueA(0);
    {
        const uint4* gBv = reinterpret_cast<const uint4*>(g_wfrag);
        #pragma unroll
        for (int i = 0; i < 16; i++) {
            int idx  = i * 256 + tid;            // (g,kt,pl,lane) linear
            int lane = idx & 31;
            int pl   = (idx >> 5) & 3;
            int kt   = (idx >> 7) & 15;
            int g    = idx >> 11;
            uint32_t gidx = (uint32_t)((((hd * 16 + kt) * 2 + g) * 16
                                        + yblk * 4 + pl) * 32 + lane);
            smBf[idx] = gBv[gidx];
        }
    }

    float acc[2][2][4][4];   // [gate][mtile][ntile][frag]
    #pragma unroll
    for (int g = 0; g < 2; g++)
        #pragma unroll
        for (int mt = 0; mt < 2; mt++)
            #pragma unroll
            for (int nt = 0; nt < 4; nt++)
                #pragma unroll
                for (int r = 0; r < 4; r++) acc[g][mt][nt][r] = 0.f;

    const int lrow0 = mw * 32 + (l & 15);        // m-tile 0 ldmatrix row
    const int lkh   = (l >> 4) * 16;

    #pragma unroll 1
    for (int c = 0; c < 4; c++) {
        const int buf = c & 1;

        cp_wait_all();        // chunk c landed (only group in flight)
        __syncthreads();      // visibility + buf^1 reads from iter c-1 done
        if (c < 3) issueA(c + 1);   // overlaps with this iteration's MMAs

        // two half-phases to bound A-frag register pressure
        #pragma unroll
        for (int jj = 0; jj < 2; jj++) {
            // A fragments: 2 sub-ksteps x 2 m-tiles
            uint32_t ab[2][2][4];
            #pragma unroll
            for (int j2 = 0; j2 < 2; j2++) {
                const int j = jj * 2 + j2;
                #pragma unroll
                for (int mt = 0; mt < 2; mt++) {
                    uint32_t rb = smA_u + buf * ASTAGE
                                  + (lrow0 + mt * 16) * AROW + j * 32 + lkh;
                    ldm_x4(ab[j2][mt], rb);
                }
            }
            // MMAs for these 2 sub-ksteps
            #pragma unroll
            for (int j2 = 0; j2 < 2; j2++) {
                const int kt = c * 4 + jj * 2 + j2;
                #pragma unroll
                for (int g = 0; g < 2; g++) {
                    #pragma unroll
                    for (int p = 0; p < 2; p++) {
                        uint4 bq = smBf[((g * 16 + kt) * 4 + ng * 2 + p) * 32 + l];
                        #pragma unroll
                        for (int mt = 0; mt < 2; mt++) {
                            mma16816(acc[g][mt][2 * p + 0], ab[j2][mt], bq.x, bq.y);
                            mma16816(acc[g][mt][2 * p + 1], ab[j2][mt], bq.z, bq.w);
                        }
                    }
                }
            }
        }
    }

    // ---- hoisted epilogue x loads (independent of SMEM; overlap barrier) ----
    float2 xpre[2][2][4];
    #pragma unroll
    for (int mt = 0; mt < 2; mt++) {
        #pragma unroll
        for (int r2 = 0; r2 < 2; r2++) {
            const int row = mw * 32 + mt * 16 + (l >> 2) + r2 * 8;
            const float* xrow = x + (size_t)(m0 + row) * Wsz + hd * BLKsz + n0;
            #pragma unroll
            for (int nt = 0; nt < 4; nt++) {
                const int c0 = ng * 32 + nt * 8 + (l & 3) * 2;
                xpre[mt][r2][nt] = *reinterpret_cast<const float2*>(xrow + c0);
            }
        }
    }
    __syncthreads();    // all GEMM smem reads done -> sscan may alias

    // ---- epilogue: gates -> {a_t, normalized_x} into SMEM scan buffer ----
    #pragma unroll
    for (int mt = 0; mt < 2; mt++) {
        #pragma unroll
        for (int r2 = 0; r2 < 2; r2++) {
            const int row = mw * 32 + mt * 16 + (l >> 2) + r2 * 8;
            const int m = m0 + row;
            const bool reset = ((m % Lsz) == 0);   // segment_pos == 0

            #pragma unroll
            for (int nt = 0; nt < 4; nt++) {
                const int c0 = ng * 32 + nt * 8 + (l & 3) * 2;
                const float xs[2] = { xpre[mt][r2][nt].x, xpre[mt][r2][nt].y };
                float4 ov;
                float* ovp = reinterpret_cast<float*>(&ov);
                #pragma unroll
                for (int e = 0; e < 2; e++) {
                    const int idx = c0 + e;
                    float zx = acc[0][mt][nt][r2 * 2 + e] + s_bx[idx];
                    float za = acc[1][mt][nt][r2 * 2 + e] + s_ba[idx];
                    float gxv = __fdividef(1.0f, 1.0f + __expf(-zx));
                    float gav = __fdividef(1.0f, 1.0f + __expf(-za));
                    float la  = -8.0f * gav * s_sp[idx];
                    float a   = __expf(la);
                    float v   = 1.0f - a * a;
                    float mult = __frsqrt_rn(fmaxf(v, 1e-30f)) * v;   // = sqrt(v)
                    ovp[e * 2 + 0] = reset ? 0.0f : a;
                    ovp[e * 2 + 1] = xs[e] * gxv * (reset ? 1.0f : mult);
                }
                *reinterpret_cast<float4*>(&sscan[row * SCROW + c0]) = ov;
            }
        }
    }
    __syncthreads();

    // ---- scan phase 1: per-(channel, 32-token segment) local combine ----
    const int sch = tid & 63;       // channel within CTA
    const int seg = tid >> 6;       // 0..3
    {
        float A = 1.0f, h = 0.0f;
        #pragma unroll 8
        for (int i = 0; i < 32; i++) {
            float2 v = sscan[(seg * 32 + i) * SCROW + sch];
            A *= v.x;
            h = fmaf(v.x, h, v.y);
        }
        sseg[seg * 64 + sch] = make_float2(A, h);
    }
    __syncthreads();

    // ---- scan phase 2: chunk combine + decoupled lookback (64 threads) ----
    if (tid < 64) {
        const int wch = hd * BLKsz + n0 + tid;     // channel within W
        const int fi  = mb * Wsz + wch;
        float A = 1.0f, h = 0.0f;
        #pragma unroll
        for (int s = 0; s < 4; s++) {
            float2 p = sseg[s * 64 + tid];
            h = fmaf(p.x, h, p.y);
            A *= p.x;
        }

        float carry;
        if (cseq == 0) {
            carry = h0[bseq * Wsz + wch];
        } else {
            g_pA[fi] = make_float2(A, h);
            st_rel(&g_flag[fi], 1);
            float Aacc = 1.0f, hacc = 0.0f;
            int j = mb - 1;
            while (true) {
                const int ji = j * Wsz + wch;
                int f;
                do { f = ld_acq(&g_flag[ji]); } while (f == 0);
                if (f == 2) {
                    carry = fmaf(Aacc, g_pH[ji], hacc);
                    break;
                }
                float2 pj = g_pA[ji];
                hacc = fmaf(Aacc, pj.y, hacc);
                Aacc *= pj.x;
                j--;
            }
        }
        g_pH[fi] = fmaf(A, carry, h);
        st_rel(&g_flag[fi], 2);
        scar[tid] = carry;
    }
    __syncthreads();

    // ---- scan phase 3: rescan with carry, write h (and last_h) ----
    {
        const int wch = hd * BLKsz + n0 + sch;
        float s = scar[sch];
        #pragma unroll
        for (int sg = 0; sg < 4; sg++) {
            if (sg < seg) {
                float2 p = sseg[sg * 64 + sch];
                s = fmaf(p.x, s, p.y);
            }
        }
        float* op = out + (size_t)(m0 + seg * 32) * Wsz + wch;
        #pragma unroll 8
        for (int i = 0; i < 32; i++) {
            float2 v = sscan[(seg * 32 + i) * SCROW + sch];
            s = fmaf(v.x, s, v.y);
            op[(size_t)i * Wsz] = s;
        }
        if (seg == 3 && cseq == CPS - 1) {
            out[TOT + (size_t)bseq * Wsz + wch] = s;   // last_h
        }
    }
}

// ---------------------------------------------------------------------------
extern "C" void kernel_launch(void* const* d_in, const int* in_sizes, int n_in,
                              void* d_out, int out_size)
{
    const float* x    = (const float*)d_in[0];
    const float* wgx  = (const float*)d_in[2];
    const float* bgx  = (const float*)d_in[3];
    const float* wga  = (const float*)d_in[4];
    const float* bga  = (const float*)d_in[5];
    const float* apar = (const float*)d_in[6];
    const float* h0   = (const float*)d_in[7];
    float* out = (float*)d_out;

    cudaFuncSetAttribute(fused_kernel,
                         cudaFuncAttributeMaxDynamicSharedMemorySize, FUSED_SMEM);

    // 0) merged prepack: x -> fp16, W -> fragments, flag clear
    prepack_kernel<<<(int)(TOT / 8 / 256), 256>>>(x, wgx, wga);

    // 1) fused gates + scan + output
    //    grid x = (y,hd) [40 — fast], grid y = m-block/chunk [128 — slow]
    dim3 g1(40, NMB);
    fused_kernel<<<g1, 256, FUSED_SMEM>>>(x, bgx, bga, apar, h0, out);
}

// round 16
// speedup vs baseline: 1.0451x; 1.0451x over previous
#include <cuda_runtime.h>
#include <cuda_fp16.h>
#include <math.h>
#include <stdint.h>

// Problem constants
#define Bsz   4
#define Lsz   4096
#define Wsz   2560
#define Hsz   10
#define BLKsz 256
#define Msz   (Bsz * Lsz)            // 16384 tokens

constexpr size_t TOT = (size_t)Bsz * Lsz * Wsz;   // 41,943,040 elements
constexpr int NMB = Msz / 128;                    // 128 m-blocks (= scan chunks)
constexpr int CPS = Lsz / 128;                    // 32 chunks per sequence

// Scratch (allocation-free: static device globals)
// Prepacked fp16 B fragments, paired n-tiles:
// [h][kt(16)][gate(2)][pair(16)][lane(32) x uint4]
__device__ uint32_t g_wfrag[10 * 16 * 2 * 16 * 128];
// fp16 row-major copy of x (for cp.async A staging + epilogue)
__device__ __align__(16) __half g_xh[TOT];
// Decoupled-lookback state, indexed [mblock(128)][wch(2560)]
__device__ float2  g_pA  [NMB * Wsz];      // per-chunk partial (A, h)
__device__ float   g_pH  [NMB * Wsz];      // per-chunk inclusive prefix h
__device__ int     g_flag[NMB * Wsz];      // 0=none, 1=partial, 2=prefix

// ===========================================================================
// Helpers
// ===========================================================================
__device__ __forceinline__ uint32_t smem_u32(const void* p) {
    uint32_t a;
    asm("{ .reg .u64 t; cvta.to.shared.u64 t, %1; cvt.u32.u64 %0, t; }"
        : "=r"(a) : "l"(p));
    return a;
}

__device__ __forceinline__ uint32_t pack_h2(float lo, float hi) {
    __half2 t;
    t.x = __float2half_rn(lo);
    t.y = __float2half_rn(hi);
    return *reinterpret_cast<uint32_t*>(&t);
}

__device__ __forceinline__ void ldm_x4(uint32_t (&r)[4], uint32_t addr) {
    asm volatile("ldmatrix.sync.aligned.m8n8.x4.shared.b16 {%0,%1,%2,%3}, [%4];"
                 : "=r"(r[0]), "=r"(r[1]), "=r"(r[2]), "=r"(r[3]) : "r"(addr));
}

__device__ __forceinline__ void mma16816(float (&c)[4], const uint32_t (&a)[4],
                                         uint32_t b0, uint32_t b1) {
    asm volatile(
        "mma.sync.aligned.m16n8k16.row.col.f32.f16.f16.f32 "
        "{%0,%1,%2,%3}, {%4,%5,%6,%7}, {%8,%9}, {%0,%1,%2,%3};"
        : "+f"(c[0]), "+f"(c[1]), "+f"(c[2]), "+f"(c[3])
        : "r"(a[0]), "r"(a[1]), "r"(a[2]), "r"(a[3]), "r"(b0), "r"(b1));
}

__device__ __forceinline__ void cp_async16(uint32_t smem_dst, const void* gsrc) {
    asm volatile("cp.async.ca.shared.global [%0], [%1], 16;"
                 :: "r"(smem_dst), "l"(gsrc) : "memory");
}
__device__ __forceinline__ void cp_commit() {
    asm volatile("cp.async.commit_group;" ::: "memory");
}
__device__ __forceinline__ void cp_wait_all() {
    asm volatile("cp.async.wait_group 0;" ::: "memory");
}

__device__ __forceinline__ int ld_acq(const int* p) {
    int v;
    asm volatile("ld.acquire.gpu.global.b32 %0, [%1];" : "=r"(v) : "l"(p) : "memory");
    return v;
}
__device__ __forceinline__ void st_rel(int* p, int v) {
    asm volatile("st.release.gpu.global.b32 [%0], %1;" :: "l"(p), "r"(v) : "memory");
}

// ===========================================================================
// Merged prepack: x -> fp16 row-major copy (all threads) and, for the first
// 327,680 threads, W -> fp16 HMMA b-fragments + lookback flag clear.
// Grid = TOT/8 threads (20480 blocks x 256).
// ===========================================================================
__global__ __launch_bounds__(256)
void prepack_kernel(const float* __restrict__ x,
                    const float* __restrict__ wgx,
                    const float* __restrict__ wga)
{
    size_t t = (size_t)blockIdx.x * blockDim.x + threadIdx.x;   // < TOT/8

    // x -> fp16 (8 elements per thread)
    {
        const float4* src = reinterpret_cast<const float4*>(x) + t * 2;
        float4 v0 = src[0];
        float4 v1 = src[1];
        uint4 u;
        u.x = pack_h2(v0.x, v0.y);
        u.y = pack_h2(v0.z, v0.w);
        u.z = pack_h2(v1.x, v1.y);
        u.w = pack_h2(v1.z, v1.w);
        reinterpret_cast<uint4*>(g_xh)[t] = u;
    }

    if (t < (size_t)NMB * Wsz) {
        int ti = (int)t;
        g_flag[ti] = 0;

        int lane = ti & 31;
        int blk  = ti >> 5;           // 0..10239
        int nt = blk & 31;
        int rest = blk >> 5;
        int g  = rest & 1;
        int rest2 = rest >> 1;
        int kt = rest2 & 15;
        int h  = rest2 >> 4;

        const float* wsrc = (g ? wga : wgx) + (size_t)h * BLKsz * BLKsz;
        int k0 = kt * 16 + (lane & 3) * 2;
        int n  = nt * 8 + (lane >> 2);
        const float* p = wsrc + (size_t)k0 * BLKsz + n;

        uint32_t b0 = pack_h2(p[0],          p[BLKsz]);
        uint32_t b1 = pack_h2(p[8 * BLKsz],  p[9 * BLKsz]);

        uint32_t base = ((uint32_t)(((h * 16 + kt) * 2 + g) * 16 + (nt >> 1)) << 7)
                        + lane * 4 + (nt & 1) * 2;
        g_wfrag[base + 0] = b0;
        g_wfrag[base + 1] = b1;
    }
}

// ===========================================================================
// Fused kernel: fp16 mma.sync gate GEMM + pointwise + in-SMEM scan.
// CTA: 128 tokens x 64 channels x one head. Warp grid 4(m) x 2(n).
// A staged CTA-wide via cp.async, K-chunk = 32 (2 ksteps / stage, 8 barriers);
// B staged once via cp.async. Epilogue x from g_xh (fp16), hoisted loads.
// Scan buffer aliases the GEMM region.
// ===========================================================================
#define AROW 80      // bytes per A smem row (64B data + 16B pad)
#define ASTAGE 10240 // 128 rows * 80B per stage
#define SCROW 66     // float2 slots per s_scan row (64 data + 2 pad)

// dynamic smem layout (bytes) — GEMM phase
#define OFF_A    0                       // 20,480 (2 stages x 128 x 80)
#define OFF_BF   20480                   // 65,536 (B fragments, whole K)
// scan phase (aliases GEMM region after final barrier): sscan at 0 (67,584)
#define OFF_SC   0
#define OFF_SEG  86016                   // 2,048
#define OFF_CAR  88064                   // 256
#define OFF_BX   88320                   // 256
#define OFF_BA   88576                   // 256
#define OFF_SP   88832                   // 256
#define FUSED_SMEM 89088

__global__ __launch_bounds__(256, 2)
void fused_kernel(const float* __restrict__ bgx,
                  const float* __restrict__ bga,
                  const float* __restrict__ apar,
                  const float* __restrict__ h0,
                  float* __restrict__ out)
{
    extern __shared__ char dynsm[];
    uint4*    smBf  = reinterpret_cast<uint4*>(dynsm + OFF_BF);     // [2][16][4][32]
    float2*   sscan = reinterpret_cast<float2*>(dynsm + OFF_SC);    // [128][66]
    float2*   sseg  = reinterpret_cast<float2*>(dynsm + OFF_SEG);   // [4][64]
    float*    scar  = reinterpret_cast<float*>(dynsm + OFF_CAR);    // [64]
    float*    s_bx  = reinterpret_cast<float*>(dynsm + OFF_BX);
    float*    s_ba  = reinterpret_cast<float*>(dynsm + OFF_BA);
    float*    s_sp  = reinterpret_cast<float*>(dynsm + OFF_SP);

    const int tid = threadIdx.x;
    const int w   = tid >> 5;
    const int l   = tid & 31;
    const int mw  = w & 3;                   // warp m-group (32 rows)
    const int ng  = w >> 2;                  // warp n-group (32 cols)
    const int hd   = blockIdx.x >> 2;        // 0..9
    const int yblk = blockIdx.x & 3;         // 0..3
    const int n0   = yblk * 64;
    const int mb   = blockIdx.y;             // m-block == scan chunk
    const int m0   = mb * 128;
    const int bseq = m0 / Lsz;               // batch index
    const int cseq = (m0 % Lsz) / 128;       // chunk within sequence

    if (tid < 64) {
        int ch = hd * BLKsz + n0 + tid;
        s_bx[tid] = bgx[ch];
        s_ba[tid] = bga[ch];
        s_sp[tid] = log1pf(expf(apar[ch]));
    }

    // A cp.async roles: row = tid/2, half = tid&1 (k 0-15 or 16-31 of chunk)
    const int arow  = tid >> 1;
    const int ahalf = tid & 1;
    const __half* xh_base = g_xh + (size_t)(m0 + arow) * Wsz
                            + hd * BLKsz + ahalf * 16;
    const uint32_t smA_u = smem_u32(dynsm + OFF_A);
    const uint32_t a_dst_base = smA_u + arow * AROW + ahalf * 32;

    auto issueA = [&](int chunk) {
        uint32_t dst = a_dst_base + (chunk & 1) * ASTAGE;
        const __half* src = xh_base + chunk * 32;
        cp_async16(dst,      src);
        cp_async16(dst + 16, src + 8);
        cp_commit();
    };

    // prologue: A chunk 0 + one-shot B stage, both via cp.async
    issueA(0);
    {
        const uint4* gBv = reinterpret_cast<const uint4*>(g_wfrag);
        const uint32_t smBf_u = smem_u32(smBf);
        #pragma unroll
        for (int i = 0; i < 16; i++) {
            int idx  = i * 256 + tid;            // (g,kt,pl,lane) linear
            int lane = idx & 31;
            int pl   = (idx >> 5) & 3;
            int kt   = (idx >> 7) & 15;
            int g    = idx >> 11;
            uint32_t gidx = (uint32_t)((((hd * 16 + kt) * 2 + g) * 16
                                        + yblk * 4 + pl) * 32 + lane);
            cp_async16(smBf_u + (uint32_t)idx * 16, gBv + gidx);
        }
        cp_commit();
    }

    float acc[2][2][4][4];   // [gate][mtile][ntile][frag]
    #pragma unroll
    for (int g = 0; g < 2; g++)
        #pragma unroll
        for (int mt = 0; mt < 2; mt++)
            #pragma unroll
            for (int nt = 0; nt < 4; nt++)
                #pragma unroll
                for (int r = 0; r < 4; r++) acc[g][mt][nt][r] = 0.f;

    const int lrow0 = mw * 32 + (l & 15);        // m-tile 0 ldmatrix row
    const int lkh   = (l >> 4) * 16;

    #pragma unroll 1
    for (int c = 0; c < 8; c++) {
        const int buf = c & 1;

        cp_wait_all();        // chunk c (+ B stage on c==0) landed
        __syncthreads();      // visibility + buf^1 reads from iter c-1 done
        if (c < 7) issueA(c + 1);   // overlaps with this iteration's MMAs

        // A fragments: 2 sub-ksteps x 2 m-tiles
        uint32_t ab[2][2][4];
        #pragma unroll
        for (int j = 0; j < 2; j++) {
            #pragma unroll
            for (int mt = 0; mt < 2; mt++) {
                uint32_t rb = smA_u + buf * ASTAGE
                              + (lrow0 + mt * 16) * AROW + j * 32 + lkh;
                ldm_x4(ab[j][mt], rb);
            }
        }

        // MMAs: 2 sub-ksteps x 2 gates x 2 pairs x 2 m-tiles x 2 n-frags
        #pragma unroll
        for (int j = 0; j < 2; j++) {
            const int kt = c * 2 + j;
            #pragma unroll
            for (int g = 0; g < 2; g++) {
                #pragma unroll
                for (int p = 0; p < 2; p++) {
                    uint4 bq = smBf[((g * 16 + kt) * 4 + ng * 2 + p) * 32 + l];
                    #pragma unroll
                    for (int mt = 0; mt < 2; mt++) {
                        mma16816(acc[g][mt][2 * p + 0], ab[j][mt], bq.x, bq.y);
                        mma16816(acc[g][mt][2 * p + 1], ab[j][mt], bq.z, bq.w);
                    }
                }
            }
        }
    }

    // ---- hoisted epilogue x loads (fp16, independent of SMEM) ----
    __half2 xpre[2][2][4];
    #pragma unroll
    for (int mt = 0; mt < 2; mt++) {
        #pragma unroll
        for (int r2 = 0; r2 < 2; r2++) {
            const int row = mw * 32 + mt * 16 + (l >> 2) + r2 * 8;
            const __half* xrow = g_xh + (size_t)(m0 + row) * Wsz + hd * BLKsz + n0;
            #pragma unroll
            for (int nt = 0; nt < 4; nt++) {
                const int c0 = ng * 32 + nt * 8 + (l & 3) * 2;
                xpre[mt][r2][nt] = *reinterpret_cast<const __half2*>(xrow + c0);
            }
        }
    }
    __syncthreads();    // all GEMM smem reads done -> sscan may alias

    // ---- epilogue: gates -> {a_t, normalized_x} into SMEM scan buffer ----
    #pragma unroll
    for (int mt = 0; mt < 2; mt++) {
        #pragma unroll
        for (int r2 = 0; r2 < 2; r2++) {
            const int row = mw * 32 + mt * 16 + (l >> 2) + r2 * 8;
            const int m = m0 + row;
            const bool reset = ((m % Lsz) == 0);   // segment_pos == 0

            #pragma unroll
            for (int nt = 0; nt < 4; nt++) {
                const int c0 = ng * 32 + nt * 8 + (l & 3) * 2;
                float2 xf = __half22float2(xpre[mt][r2][nt]);
                const float xs[2] = { xf.x, xf.y };
                float4 ov;
                float* ovp = reinterpret_cast<float*>(&ov);
                #pragma unroll
                for (int e = 0; e < 2; e++) {
                    const int idx = c0 + e;
                    float zx = acc[0][mt][nt][r2 * 2 + e] + s_bx[idx];
                    float za = acc[1][mt][nt][r2 * 2 + e] + s_ba[idx];
                    float gxv = __fdividef(1.0f, 1.0f + __expf(-zx));
                    float gav = __fdividef(1.0f, 1.0f + __expf(-za));
                    float la  = -8.0f * gav * s_sp[idx];
                    float a   = __expf(la);
                    float v   = 1.0f - a * a;
                    float mult = __frsqrt_rn(fmaxf(v, 1e-30f)) * v;   // = sqrt(v)
                    ovp[e * 2 + 0] = reset ? 0.0f : a;
                    ovp[e * 2 + 1] = xs[e] * gxv * (reset ? 1.0f : mult);
                }
                *reinterpret_cast<float4*>(&sscan[row * SCROW + c0]) = ov;
            }
        }
    }
    __syncthreads();

    // ---- scan phase 1: per-(channel, 32-token segment) local combine ----
    const int sch = tid & 63;       // channel within CTA
    const int seg = tid >> 6;       // 0..3
    {
        float A = 1.0f, h = 0.0f;
        #pragma unroll 8
        for (int i = 0; i < 32; i++) {
            float2 v = sscan[(seg * 32 + i) * SCROW + sch];
            A *= v.x;
            h = fmaf(v.x, h, v.y);
        }
        sseg[seg * 64 + sch] = make_float2(A, h);
    }
    __syncthreads();

    // ---- scan phase 2: chunk combine + decoupled lookback (64 threads) ----
    if (tid < 64) {
        const int wch = hd * BLKsz + n0 + tid;     // channel within W
        const int fi  = mb * Wsz + wch;
        float A = 1.0f, h = 0.0f;
        #pragma unroll
        for (int s = 0; s < 4; s++) {
            float2 p = sseg[s * 64 + tid];
            h = fmaf(p.x, h, p.y);
            A *= p.x;
        }

        float carry;
        if (cseq == 0) {
            carry = h0[bseq * Wsz + wch];
        } else {
            g_pA[fi] = make_float2(A, h);
            st_rel(&g_flag[fi], 1);
            float Aacc = 1.0f, hacc = 0.0f;
            int j = mb - 1;
            while (true) {
                const int ji = j * Wsz + wch;
                int f;
                do { f = ld_acq(&g_flag[ji]); } while (f == 0);
                if (f == 2) {
                    carry = fmaf(Aacc, g_pH[ji], hacc);
                    break;
                }
                float2 pj = g_pA[ji];
                hacc = fmaf(Aacc, pj.y, hacc);
                Aacc *= pj.x;
                j--;
            }
        }
        g_pH[fi] = fmaf(A, carry, h);
        st_rel(&g_flag[fi], 2);
        scar[tid] = carry;
    }
    __syncthreads();

    // ---- scan phase 3: rescan with carry, write h (and last_h) ----
    {
        const int wch = hd * BLKsz + n0 + sch;
        float s = scar[sch];
        #pragma unroll
        for (int sg = 0; sg < 4; sg++) {
            if (sg < seg) {
                float2 p = sseg[sg * 64 + sch];
                s = fmaf(p.x, s, p.y);
            }
        }
        float* op = out + (size_t)(m0 + seg * 32) * Wsz + wch;
        #pragma unroll 8
        for (int i = 0; i < 32; i++) {
            float2 v = sscan[(seg * 32 + i) * SCROW + sch];
            s = fmaf(v.x, s, v.y);
            op[(size_t)i * Wsz] = s;
        }
        if (seg == 3 && cseq == CPS - 1) {
            out[TOT + (size_t)bseq * Wsz + wch] = s;   // last_h
        }
    }
}

// ---------------------------------------------------------------------------
extern "C" void kernel_launch(void* const* d_in, const int* in_sizes, int n_in,
                              void* d_out, int out_size)
{
    const float* x    = (const float*)d_in[0];
    const float* wgx  = (const float*)d_in[2];
    const float* bgx  = (const float*)d_in[3];
    const float* wga  = (const float*)d_in[4];
    const float* bga  = (const float*)d_in[5];
    const float* apar = (const float*)d_in[6];
    const float* h0   = (const float*)d_in[7];
    float* out = (float*)d_out;

    cudaFuncSetAttribute(fused_kernel,
                         cudaFuncAttributeMaxDynamicSharedMemorySize, FUSED_SMEM);

    // 0) merged prepack: x -> fp16, W -> fragments, flag clear
    prepack_kernel<<<(int)(TOT / 8 / 256), 256>>>(x, wgx, wga);

    // 1) fused gates + scan + output
    //    grid x = (y,hd) [40 — fast], grid y = m-block/chunk [128 — slow]
    dim3 g1(40, NMB);
    fused_kernel<<<g1, 256, FUSED_SMEM>>>(bgx, bga, apar, h0, out);
}

// round 17
// speedup vs baseline: 1.0591x; 1.0134x over previous
#include <cuda_runtime.h>
#include <cuda_fp16.h>
#include <math.h>
#include <stdint.h>

// Problem constants
#define Bsz   4
#define Lsz   4096
#define Wsz   2560
#define Hsz   10
#define BLKsz 256
#define Msz   (Bsz * Lsz)            // 16384 tokens

constexpr size_t TOT = (size_t)Bsz * Lsz * Wsz;   // 41,943,040 elements
constexpr int NMB = Msz / 128;                    // 128 m-blocks (= scan chunks)
constexpr int CPS = Lsz / 128;                    // 32 chunks per sequence

// Scratch (allocation-free: static device globals)
// Prepacked fp16 B fragments, paired n-tiles:
// [h][kt(16)][gate(2)][pair(16)][lane(32) x uint4]
__device__ uint32_t g_wfrag[10 * 16 * 2 * 16 * 128];
// fp16 row-major copy of x (for cp.async A staging + epilogue)
__device__ __align__(16) __half g_xh[TOT];
// Decoupled-lookback state, indexed [mblock(128)][wch(2560)]
__device__ float2  g_pA  [NMB * Wsz];      // per-chunk partial (A, h)
__device__ float   g_pH  [NMB * Wsz];      // per-chunk inclusive prefix h
__device__ int     g_flag[NMB * Wsz];      // 0=none, 1=partial, 2=prefix

// ===========================================================================
// Helpers
// ===========================================================================
__device__ __forceinline__ uint32_t smem_u32(const void* p) {
    uint32_t a;
    asm("{ .reg .u64 t; cvta.to.shared.u64 t, %1; cvt.u32.u64 %0, t; }"
        : "=r"(a) : "l"(p));
    return a;
}

__device__ __forceinline__ uint32_t pack_h2(float lo, float hi) {
    __half2 t;
    t.x = __float2half_rn(lo);
    t.y = __float2half_rn(hi);
    return *reinterpret_cast<uint32_t*>(&t);
}

__device__ __forceinline__ void ldm_x4(uint32_t (&r)[4], uint32_t addr) {
    asm volatile("ldmatrix.sync.aligned.m8n8.x4.shared.b16 {%0,%1,%2,%3}, [%4];"
                 : "=r"(r[0]), "=r"(r[1]), "=r"(r[2]), "=r"(r[3]) : "r"(addr));
}

__device__ __forceinline__ void mma16816(float (&c)[4], const uint32_t (&a)[4],
                                         uint32_t b0, uint32_t b1) {
    asm volatile(
        "mma.sync.aligned.m16n8k16.row.col.f32.f16.f16.f32 "
        "{%0,%1,%2,%3}, {%4,%5,%6,%7}, {%8,%9}, {%0,%1,%2,%3};"
        : "+f"(c[0]), "+f"(c[1]), "+f"(c[2]), "+f"(c[3])
        : "r"(a[0]), "r"(a[1]), "r"(a[2]), "r"(a[3]), "r"(b0), "r"(b1));
}

__device__ __forceinline__ void cp_async16(uint32_t smem_dst, const void* gsrc) {
    asm volatile("cp.async.ca.shared.global [%0], [%1], 16;"
                 :: "r"(smem_dst), "l"(gsrc) : "memory");
}
__device__ __forceinline__ void cp_commit() {
    asm volatile("cp.async.commit_group;" ::: "memory");
}
__device__ __forceinline__ void cp_wait_all() {
    asm volatile("cp.async.wait_group 0;" ::: "memory");
}

__device__ __forceinline__ int ld_acq(const int* p) {
    int v;
    asm volatile("ld.acquire.gpu.global.b32 %0, [%1];" : "=r"(v) : "l"(p) : "memory");
    return v;
}
__device__ __forceinline__ void st_rel(int* p, int v) {
    asm volatile("st.release.gpu.global.b32 [%0], %1;" :: "l"(p), "r"(v) : "memory");
}

// ===========================================================================
// Merged prepack: x -> fp16 row-major copy (all threads) and, for the first
// 327,680 threads, W -> fp16 HMMA b-fragments + lookback flag clear.
// Grid = TOT/8 threads (20480 blocks x 256).
// ===========================================================================
__global__ __launch_bounds__(256)
void prepack_kernel(const float* __restrict__ x,
                    const float* __restrict__ wgx,
                    const float* __restrict__ wga)
{
    size_t t = (size_t)blockIdx.x * blockDim.x + threadIdx.x;   // < TOT/8

    // x -> fp16 (8 elements per thread)
    {
        const float4* src = reinterpret_cast<const float4*>(x) + t * 2;
        float4 v0 = src[0];
        float4 v1 = src[1];
        uint4 u;
        u.x = pack_h2(v0.x, v0.y);
        u.y = pack_h2(v0.z, v0.w);
        u.z = pack_h2(v1.x, v1.y);
        u.w = pack_h2(v1.z, v1.w);
        reinterpret_cast<uint4*>(g_xh)[t] = u;
    }

    if (t < (size_t)NMB * Wsz) {
        int ti = (int)t;
        g_flag[ti] = 0;

        int lane = ti & 31;
        int blk  = ti >> 5;           // 0..10239
        int nt = blk & 31;
        int rest = blk >> 5;
        int g  = rest & 1;
        int rest2 = rest >> 1;
        int kt = rest2 & 15;
        int h  = rest2 >> 4;

        const float* wsrc = (g ? wga : wgx) + (size_t)h * BLKsz * BLKsz;
        int k0 = kt * 16 + (lane & 3) * 2;
        int n  = nt * 8 + (lane >> 2);
        const float* p = wsrc + (size_t)k0 * BLKsz + n;

        uint32_t b0 = pack_h2(p[0],          p[BLKsz]);
        uint32_t b1 = pack_h2(p[8 * BLKsz],  p[9 * BLKsz]);

        uint32_t base = ((uint32_t)(((h * 16 + kt) * 2 + g) * 16 + (nt >> 1)) << 7)
                        + lane * 4 + (nt & 1) * 2;
        g_wfrag[base + 0] = b0;
        g_wfrag[base + 1] = b1;
    }
}

// ===========================================================================
// Fused kernel: fp16 mma.sync gate GEMM + pointwise + in-SMEM scan.
// CTA: 128 tokens x 64 channels x one head. Warp grid 4(m) x 2(n).
// A staged CTA-wide via cp.async, K-chunk = 32 (2 ksteps / stage, 8 barriers);
// B staged once via cp.async. Epilogue x from g_xh (fp16), hoisted loads;
// per-channel params hoisted to registers. Scan phase 1 stores inclusive
// prefixes in place -> phase 3 is fully parallel.
// ===========================================================================
#define AROW 80      // bytes per A smem row (64B data + 16B pad)
#define ASTAGE 10240 // 128 rows * 80B per stage
#define SCROW 66     // float2 slots per s_scan row (64 data + 2 pad)

// dynamic smem layout (bytes) — GEMM phase
#define OFF_A    0                       // 20,480 (2 stages x 128 x 80)
#define OFF_BF   20480                   // 65,536 (B fragments, whole K)
// scan phase (aliases GEMM region after final barrier): sscan at 0 (67,584)
#define OFF_SC   0
#define OFF_SEG  86016                   // 2,048
#define OFF_CAR  88064                   // 256
#define OFF_BX   88320                   // 256
#define OFF_BA   88576                   // 256
#define OFF_SP   88832                   // 256
#define FUSED_SMEM 89088

__global__ __launch_bounds__(256, 2)
void fused_kernel(const float* __restrict__ bgx,
                  const float* __restrict__ bga,
                  const float* __restrict__ apar,
                  const float* __restrict__ h0,
                  float* __restrict__ out)
{
    extern __shared__ char dynsm[];
    uint4*    smBf  = reinterpret_cast<uint4*>(dynsm + OFF_BF);     // [2][16][4][32]
    float2*   sscan = reinterpret_cast<float2*>(dynsm + OFF_SC);    // [128][66]
    float2*   sseg  = reinterpret_cast<float2*>(dynsm + OFF_SEG);   // [4][64]
    float*    scar  = reinterpret_cast<float*>(dynsm + OFF_CAR);    // [64]
    float*    s_bx  = reinterpret_cast<float*>(dynsm + OFF_BX);
    float*    s_ba  = reinterpret_cast<float*>(dynsm + OFF_BA);
    float*    s_sp  = reinterpret_cast<float*>(dynsm + OFF_SP);

    const int tid = threadIdx.x;
    const int w   = tid >> 5;
    const int l   = tid & 31;
    const int mw  = w & 3;                   // warp m-group (32 rows)
    const int ng  = w >> 2;                  // warp n-group (32 cols)
    const int hd   = blockIdx.x >> 2;        // 0..9
    const int yblk = blockIdx.x & 3;         // 0..3
    const int n0   = yblk * 64;
    const int mb   = blockIdx.y;             // m-block == scan chunk
    const int m0   = mb * 128;
    const int bseq = m0 / Lsz;               // batch index
    const int cseq = (m0 % Lsz) / 128;       // chunk within sequence

    if (tid < 64) {
        int ch = hd * BLKsz + n0 + tid;
        s_bx[tid] = bgx[ch];
        s_ba[tid] = bga[ch];
        s_sp[tid] = log1pf(expf(apar[ch]));
    }

    // A cp.async roles: row = tid/2, half = tid&1 (k 0-15 or 16-31 of chunk)
    const int arow  = tid >> 1;
    const int ahalf = tid & 1;
    const __half* xh_base = g_xh + (size_t)(m0 + arow) * Wsz
                            + hd * BLKsz + ahalf * 16;
    const uint32_t smA_u = smem_u32(dynsm + OFF_A);
    const uint32_t a_dst_base = smA_u + arow * AROW + ahalf * 32;

    auto issueA = [&](int chunk) {
        uint32_t dst = a_dst_base + (chunk & 1) * ASTAGE;
        const __half* src = xh_base + chunk * 32;
        cp_async16(dst,      src);
        cp_async16(dst + 16, src + 8);
        cp_commit();
    };

    // prologue: A chunk 0 + one-shot B stage, both via cp.async
    issueA(0);
    {
        const uint4* gBv = reinterpret_cast<const uint4*>(g_wfrag);
        const uint32_t smBf_u = smem_u32(smBf);
        #pragma unroll
        for (int i = 0; i < 16; i++) {
            int idx  = i * 256 + tid;            // (g,kt,pl,lane) linear
            int lane = idx & 31;
            int pl   = (idx >> 5) & 3;
            int kt   = (idx >> 7) & 15;
            int g    = idx >> 11;
            uint32_t gidx = (uint32_t)((((hd * 16 + kt) * 2 + g) * 16
                                        + yblk * 4 + pl) * 32 + lane);
            cp_async16(smBf_u + (uint32_t)idx * 16, gBv + gidx);
        }
        cp_commit();
    }

    float acc[2][2][4][4];   // [gate][mtile][ntile][frag]
    #pragma unroll
    for (int g = 0; g < 2; g++)
        #pragma unroll
        for (int mt = 0; mt < 2; mt++)
            #pragma unroll
            for (int nt = 0; nt < 4; nt++)
                #pragma unroll
                for (int r = 0; r < 4; r++) acc[g][mt][nt][r] = 0.f;

    const int lrow0 = mw * 32 + (l & 15);        // m-tile 0 ldmatrix row
    const int lkh   = (l >> 4) * 16;

    #pragma unroll 1
    for (int c = 0; c < 8; c++) {
        const int buf = c & 1;

        cp_wait_all();        // chunk c (+ B stage on c==0) landed
        __syncthreads();      // visibility + buf^1 reads from iter c-1 done
        if (c < 7) issueA(c + 1);   // overlaps with this iteration's MMAs

        // A fragments: 2 sub-ksteps x 2 m-tiles
        uint32_t ab[2][2][4];
        #pragma unroll
        for (int j = 0; j < 2; j++) {
            #pragma unroll
            for (int mt = 0; mt < 2; mt++) {
                uint32_t rb = smA_u + buf * ASTAGE
                              + (lrow0 + mt * 16) * AROW + j * 32 + lkh;
                ldm_x4(ab[j][mt], rb);
            }
        }

        // MMAs: 2 sub-ksteps x 2 gates x 2 pairs x 2 m-tiles x 2 n-frags
        #pragma unroll
        for (int j = 0; j < 2; j++) {
            const int kt = c * 2 + j;
            #pragma unroll
            for (int g = 0; g < 2; g++) {
                #pragma unroll
                for (int p = 0; p < 2; p++) {
                    uint4 bq = smBf[((g * 16 + kt) * 4 + ng * 2 + p) * 32 + l];
                    #pragma unroll
                    for (int mt = 0; mt < 2; mt++) {
                        mma16816(acc[g][mt][2 * p + 0], ab[j][mt], bq.x, bq.y);
                        mma16816(acc[g][mt][2 * p + 1], ab[j][mt], bq.z, bq.w);
                    }
                }
            }
        }
    }

    // ---- hoisted epilogue x loads (fp16, independent of SMEM) ----
    __half2 xpre[2][2][4];
    #pragma unroll
    for (int mt = 0; mt < 2; mt++) {
        #pragma unroll
        for (int r2 = 0; r2 < 2; r2++) {
            const int row = mw * 32 + mt * 16 + (l >> 2) + r2 * 8;
            const __half* xrow = g_xh + (size_t)(m0 + row) * Wsz + hd * BLKsz + n0;
            #pragma unroll
            for (int nt = 0; nt < 4; nt++) {
                const int c0 = ng * 32 + nt * 8 + (l & 3) * 2;
                xpre[mt][r2][nt] = *reinterpret_cast<const __half2*>(xrow + c0);
            }
        }
    }

    // ---- hoisted per-channel params: 8 distinct channels per thread ----
    // q = nt*2 + e  ->  channel idx = ng*32 + nt*8 + (l&3)*2 + e
    float pbx[8], pba[8], psp[8];
    #pragma unroll
    for (int q = 0; q < 8; q++) {
        const int idx = ng * 32 + (q >> 1) * 8 + (l & 3) * 2 + (q & 1);
        pbx[q] = s_bx[idx];
        pba[q] = s_ba[idx];
        psp[q] = s_sp[idx];
    }
    __syncthreads();    // all GEMM smem reads done -> sscan may alias

    // ---- epilogue: gates -> {a_t, normalized_x} into SMEM scan buffer ----
    #pragma unroll
    for (int mt = 0; mt < 2; mt++) {
        #pragma unroll
        for (int r2 = 0; r2 < 2; r2++) {
            const int row = mw * 32 + mt * 16 + (l >> 2) + r2 * 8;
            const int m = m0 + row;
            const bool reset = ((m % Lsz) == 0);   // segment_pos == 0

            #pragma unroll
            for (int nt = 0; nt < 4; nt++) {
                const int c0 = ng * 32 + nt * 8 + (l & 3) * 2;
                float2 xf = __half22float2(xpre[mt][r2][nt]);
                const float xs[2] = { xf.x, xf.y };
                float4 ov;
                float* ovp = reinterpret_cast<float*>(&ov);
                #pragma unroll
                for (int e = 0; e < 2; e++) {
                    const int q = nt * 2 + e;
                    float zx = acc[0][mt][nt][r2 * 2 + e] + pbx[q];
                    float za = acc[1][mt][nt][r2 * 2 + e] + pba[q];
                    float gxv = __fdividef(1.0f, 1.0f + __expf(-zx));
                    float gav = __fdividef(1.0f, 1.0f + __expf(-za));
                    float la  = -8.0f * gav * psp[q];
                    float a   = __expf(la);
                    float v   = 1.0f - a * a;
                    float mult = __frsqrt_rn(fmaxf(v, 1e-30f)) * v;   // = sqrt(v)
                    ovp[e * 2 + 0] = reset ? 0.0f : a;
                    ovp[e * 2 + 1] = xs[e] * gxv * (reset ? 1.0f : mult);
                }
                *reinterpret_cast<float4*>(&sscan[row * SCROW + c0]) = ov;
            }
        }
    }
    __syncthreads();

    // ---- scan phase 1: per-(channel, 32-token segment) inclusive prefixes,
    //      written back in place -> phase 3 becomes fully parallel ----
    const int sch = tid & 63;       // channel within CTA
    const int seg = tid >> 6;       // 0..3
    {
        float A = 1.0f, h = 0.0f;
        #pragma unroll 8
        for (int i = 0; i < 32; i++) {
            float2 v = sscan[(seg * 32 + i) * SCROW + sch];
            h = fmaf(v.x, h, v.y);
            A *= v.x;
            sscan[(seg * 32 + i) * SCROW + sch] = make_float2(A, h);
        }
        sseg[seg * 64 + sch] = make_float2(A, h);
    }
    __syncthreads();

    // ---- scan phase 2: chunk combine + decoupled lookback (64 threads) ----
    if (tid < 64) {
        const int wch = hd * BLKsz + n0 + tid;     // channel within W
        const int fi  = mb * Wsz + wch;
        float A = 1.0f, h = 0.0f;
        #pragma unroll
        for (int s = 0; s < 4; s++) {
            float2 p = sseg[s * 64 + tid];
            h = fmaf(p.x, h, p.y);
            A *= p.x;
        }

        float carry;
        if (cseq == 0) {
            carry = h0[bseq * Wsz + wch];
        } else {
            g_pA[fi] = make_float2(A, h);
            st_rel(&g_flag[fi], 1);
            float Aacc = 1.0f, hacc = 0.0f;
            int j = mb - 1;
            while (true) {
                const int ji = j * Wsz + wch;
                int f;
                do { f = ld_acq(&g_flag[ji]); } while (f == 0);
                if (f == 2) {
                    carry = fmaf(Aacc, g_pH[ji], hacc);
                    break;
                }
                float2 pj = g_pA[ji];
                hacc = fmaf(Aacc, pj.y, hacc);
                Aacc *= pj.x;
                j--;
            }
        }
        g_pH[fi] = fmaf(A, carry, h);
        st_rel(&g_flag[fi], 2);
        scar[tid] = carry;
    }
    __syncthreads();

    // ---- scan phase 3: parallel apply — h_i = Ap_i*carry_seg + hl_i ----
    {
        const int wch = hd * BLKsz + n0 + sch;
        float s = scar[sch];
        // carry into this 32-token segment: combine earlier segment totals
        #pragma unroll
        for (int sg = 0; sg < 4; sg++) {
            if (sg < seg) {
                float2 p = sseg[sg * 64 + sch];
                s = fmaf(p.x, s, p.y);
            }
        }
        float* op = out + (size_t)(m0 + seg * 32) * Wsz + wch;
        float last = 0.0f;
        #pragma unroll 8
        for (int i = 0; i < 32; i++) {
            float2 v = sscan[(seg * 32 + i) * SCROW + sch];
            float hv = fmaf(v.x, s, v.y);     // independent per i
            op[(size_t)i * Wsz] = hv;
            if (i == 31) last = hv;
        }
        if (seg == 3 && cseq == CPS - 1) {
            out[TOT + (size_t)bseq * Wsz + wch] = last;   // last_h
        }
    }
}

// ---------------------------------------------------------------------------
extern "C" void kernel_launch(void* const* d_in, const int* in_sizes, int n_in,
                              void* d_out, int out_size)
{
    const float* x    = (const float*)d_in[0];
    const float* wgx  = (const float*)d_in[2];
    const float* bgx  = (const float*)d_in[3];
    const float* wga  = (const float*)d_in[4];
    const float* bga  = (const float*)d_in[5];
    const float* apar = (const float*)d_in[6];
    const float* h0   = (const float*)d_in[7];
    float* out = (float*)d_out;

    cudaFuncSetAttribute(fused_kernel,
                         cudaFuncAttributeMaxDynamicSharedMemorySize, FUSED_SMEM);

    // 0) merged prepack: x -> fp16, W -> fragments, flag clear
    prepack_kernel<<<(int)(TOT / 8 / 256), 256>>>(x, wgx, wga);

    // 1) fused gates + scan + output
    //    grid x = (y,hd) [40 — fast], grid y = m-block/chunk [128 — slow]
    dim3 g1(40, NMB);
    fused_kernel<<<g1, 256, FUSED_SMEM>>>(bgx, bga, apar, h0, out);
}